// round 2
// baseline (speedup 1.0000x reference)
#include <cuda_runtime.h>
#include <cuda_bf16.h>
#include <cstdint>

// Problem constants
#define BATCH 32768
#define EMB   2048
#define KDIM  320          // 5*8*8
#define K_ACTIVE 103       // ceil(0.05*2048)

// Scratch (device globals — no cudaMalloc allowed)
__device__ __align__(16) float g_h[(size_t)BATCH * KDIM];   // 42 MB
__device__ __align__(16) float g_z[(size_t)BATCH * EMB];    // 268 MB

// ---------------------------------------------------------------------------
// Kernel 1: conv3x3(1->5) + BN + ReLU + maxpool3x3/3 -> h[b, c*64+py*8+px]
// One block per image, 320 threads = one per output element.
// ---------------------------------------------------------------------------
__global__ __launch_bounds__(320) void conv_bn_pool_kernel(
    const float* __restrict__ x,       // [B,28,28]
    const float* __restrict__ conv_w,  // [5,1,3,3]
    const float* __restrict__ gamma,
    const float* __restrict__ beta,
    const float* __restrict__ mean,
    const float* __restrict__ var)
{
    __shared__ float xs[28 * 28];
    const int b   = blockIdx.x;
    const int tid = threadIdx.x;

    const float* xb = x + (size_t)b * 784;
    for (int i = tid; i < 784; i += 320) xs[i] = xb[i];
    __syncthreads();

    // tid -> (c, py, px)
    const int c   = tid >> 6;
    const int rem = tid & 63;
    const int py  = rem >> 3;
    const int px  = rem & 7;

    float w[9];
#pragma unroll
    for (int i = 0; i < 9; i++) w[i] = conv_w[c * 9 + i];
    const float sc = gamma[c] * rsqrtf(var[c] + 1e-5f);
    const float mu = mean[c];
    const float bt = beta[c];

    const int oy0 = py * 3;
    const int ox0 = px * 3;

    float m = -3.4e38f;
#pragma unroll
    for (int dy = 0; dy < 3; dy++) {
#pragma unroll
        for (int dx = 0; dx < 3; dx++) {
            const int iy = oy0 + dy;
            const int ix = ox0 + dx;
            float s = 0.f;
#pragma unroll
            for (int ky = 0; ky < 3; ky++) {
#pragma unroll
                for (int kx = 0; kx < 3; kx++) {
                    s += xs[(iy + ky) * 28 + (ix + kx)] * w[ky * 3 + kx];
                }
            }
            float v = (s - mu) * sc + bt;
            m = fmaxf(m, v);
        }
    }
    // relu commutes with max
    g_h[(size_t)b * KDIM + tid] = fmaxf(m, 0.f);
}

// ---------------------------------------------------------------------------
// Kernel 2: z = h @ fc_w^T  (A [B,320] row-major, W [2048,320] row-major)
// Classic smem-tiled SGEMM: 128x128 tile, BK=16, 256 threads, 8x8 microtile.
// ---------------------------------------------------------------------------
#define BM 128
#define BN 128
#define BK 16

__global__ __launch_bounds__(256) void gemm_kernel(const float* __restrict__ W)
{
    __shared__ float As[BK][BM];
    __shared__ float Bs[BK][BN];

    const int bn  = blockIdx.x;   // 0..15
    const int bm  = blockIdx.y;   // 0..255
    const int tid = threadIdx.x;
    const int tx  = tid & 15;     // col group
    const int ty  = tid >> 4;     // row group

    const float* Ab = g_h + (size_t)bm * BM * KDIM;
    const float* Bb = W   + (size_t)bn * BN * KDIM;

    float acc[8][8];
#pragma unroll
    for (int i = 0; i < 8; i++)
#pragma unroll
        for (int j = 0; j < 8; j++) acc[i][j] = 0.f;

    for (int k0 = 0; k0 < KDIM; k0 += BK) {
        // load tiles (each thread: 2 float4 of A, 2 float4 of B), transpose to [k][m]
#pragma unroll
        for (int i = 0; i < 2; i++) {
            const int idx = tid * 2 + i;      // 0..511
            const int row = idx >> 2;         // 0..127
            const int kq  = idx & 3;          // 0..3
            float4 va = *(const float4*)(Ab + (size_t)row * KDIM + k0 + kq * 4);
            As[kq * 4 + 0][row] = va.x;
            As[kq * 4 + 1][row] = va.y;
            As[kq * 4 + 2][row] = va.z;
            As[kq * 4 + 3][row] = va.w;
            float4 vb = *(const float4*)(Bb + (size_t)row * KDIM + k0 + kq * 4);
            Bs[kq * 4 + 0][row] = vb.x;
            Bs[kq * 4 + 1][row] = vb.y;
            Bs[kq * 4 + 2][row] = vb.z;
            Bs[kq * 4 + 3][row] = vb.w;
        }
        __syncthreads();

#pragma unroll
        for (int kk = 0; kk < BK; kk++) {
            float a[8], bfr[8];
            *(float4*)&a[0]   = *(const float4*)&As[kk][ty * 8];
            *(float4*)&a[4]   = *(const float4*)&As[kk][ty * 8 + 4];
            *(float4*)&bfr[0] = *(const float4*)&Bs[kk][tx * 8];
            *(float4*)&bfr[4] = *(const float4*)&Bs[kk][tx * 8 + 4];
#pragma unroll
            for (int i = 0; i < 8; i++)
#pragma unroll
                for (int j = 0; j < 8; j++)
                    acc[i][j] = fmaf(a[i], bfr[j], acc[i][j]);
        }
        __syncthreads();
    }

    // write out
#pragma unroll
    for (int i = 0; i < 8; i++) {
        const size_t off = (size_t)(bm * BM + ty * 8 + i) * EMB + bn * BN + tx * 8;
        float4 c0 = make_float4(acc[i][0], acc[i][1], acc[i][2], acc[i][3]);
        float4 c1 = make_float4(acc[i][4], acc[i][5], acc[i][6], acc[i][7]);
        *(float4*)(g_z + off)     = c0;
        *(float4*)(g_z + off + 4) = c1;
    }
}

// ---------------------------------------------------------------------------
// Kernel 3: per-row exact radix-select (103rd largest) + binarize
// One block (256 threads) per row of 2048.
// ---------------------------------------------------------------------------
__device__ __forceinline__ unsigned f2key(float f)
{
    unsigned u = __float_as_uint(f);
    return (u & 0x80000000u) ? ~u : (u | 0x80000000u);  // monotonic increasing
}

__global__ __launch_bounds__(256) void kwta_kernel(float* __restrict__ out)
{
    __shared__ unsigned hist[256];
    __shared__ unsigned scan[256];
    __shared__ unsigned sh_bin;
    __shared__ unsigned sh_k;

    const int row = blockIdx.x;
    const int tid = threadIdx.x;

    const float4* zr = (const float4*)(g_z + (size_t)row * EMB);
    float4 v0 = zr[tid * 2];
    float4 v1 = zr[tid * 2 + 1];

    unsigned key[8];
    key[0] = f2key(v0.x); key[1] = f2key(v0.y); key[2] = f2key(v0.z); key[3] = f2key(v0.w);
    key[4] = f2key(v1.x); key[5] = f2key(v1.y); key[6] = f2key(v1.z); key[7] = f2key(v1.w);

    unsigned prefix = 0;
    unsigned k = K_ACTIVE;

#pragma unroll
    for (int shift = 24; shift >= 0; shift -= 8) {
        hist[tid] = 0;
        __syncthreads();

#pragma unroll
        for (int e = 0; e < 8; e++) {
            bool match = (shift == 24) ? true : ((key[e] >> (shift + 8)) == prefix);
            if (match) atomicAdd(&hist[(key[e] >> shift) & 255u], 1u);
        }
        __syncthreads();

        // inclusive suffix scan: scan[b] = sum_{b'>=b} hist[b']
        scan[tid] = hist[tid];
        __syncthreads();
#pragma unroll
        for (int off = 1; off < 256; off <<= 1) {
            unsigned add = (tid + off < 256) ? scan[tid + off] : 0u;
            __syncthreads();
            scan[tid] += add;
            __syncthreads();
        }

        unsigned St    = scan[tid];
        unsigned Snext = (tid < 255) ? scan[tid + 1] : 0u;
        if (St >= k && Snext < k) {
            sh_bin = (unsigned)tid;
            sh_k   = k - Snext;
        }
        __syncthreads();

        prefix = (prefix << 8) | sh_bin;
        k = sh_k;
        __syncthreads();  // protect hist reuse next pass
    }

    const unsigned thr = prefix;  // key of the 103rd-largest element
    float4 o0, o1;
    o0.x = (key[0] >= thr) ? 1.f : 0.f;
    o0.y = (key[1] >= thr) ? 1.f : 0.f;
    o0.z = (key[2] >= thr) ? 1.f : 0.f;
    o0.w = (key[3] >= thr) ? 1.f : 0.f;
    o1.x = (key[4] >= thr) ? 1.f : 0.f;
    o1.y = (key[5] >= thr) ? 1.f : 0.f;
    o1.z = (key[6] >= thr) ? 1.f : 0.f;
    o1.w = (key[7] >= thr) ? 1.f : 0.f;

    float4* od = (float4*)(out + (size_t)row * EMB);
    od[tid * 2]     = o0;
    od[tid * 2 + 1] = o1;
}

// ---------------------------------------------------------------------------
extern "C" void kernel_launch(void* const* d_in, const int* in_sizes, int n_in,
                              void* d_out, int out_size)
{
    const float* x      = (const float*)d_in[0];
    const float* conv_w = (const float*)d_in[1];
    const float* gamma  = (const float*)d_in[2];
    const float* beta   = (const float*)d_in[3];
    const float* mean   = (const float*)d_in[4];
    const float* var    = (const float*)d_in[5];
    const float* fc_w   = (const float*)d_in[6];
    float* out = (float*)d_out;

    conv_bn_pool_kernel<<<BATCH, 320>>>(x, conv_w, gamma, beta, mean, var);
    gemm_kernel<<<dim3(EMB / BN, BATCH / BM), 256>>>(fc_w);
    kwta_kernel<<<BATCH, 256>>>(out);
}

// round 10
// speedup vs baseline: 1.5088x; 1.5088x over previous
#include <cuda_runtime.h>
#include <cstdint>

// Problem constants
#define BATCH 32768
#define EMB   2048
#define KDIM  320          // 5*8*8
#define K_ACTIVE 103       // ceil(0.05*2048)
#define KBLKS  (KDIM / 8)  // 40 k8 blocks

// GEMM tiling
#define TM 128             // CTA M tile
#define TN 256             // CTA N tile
#define KC 32              // K chunk (4 k8 blocks)
#define CHUNKS (KDIM / KC) // 10

#define DELTA 0.025f       // refinement window half-width
#define MAXC  128          // candidate cap per row

// Scratch (device globals — no cudaMalloc allowed)
__device__ __align__(16) float g_h  [(size_t)BATCH * KDIM];  // plain h rows (refinement)
__device__ __align__(16) float g_Apk[(size_t)BATCH * KDIM];  // tf32-rounded, frag-packed
__device__ __align__(16) float g_Bpk[(size_t)EMB   * KDIM];  // tf32-rounded, frag-packed
__device__ __align__(16) float g_z  [(size_t)BATCH * EMB];

// ---------------------------------------------------------------------------
__device__ __forceinline__ uint32_t smem_u32(const void* p) {
    uint32_t a;
    asm("{ .reg .u64 t; cvta.to.shared.u64 t, %1; cvt.u32.u64 %0, t; }"
        : "=r"(a) : "l"(p));
    return a;
}

__device__ __forceinline__ float tf32r(float x) {
    float r;
    asm("cvt.rna.tf32.f32 %0, %1;" : "=f"(r) : "f"(x));
    return r;
}

__device__ __forceinline__ void cpa16(uint32_t dst, const float* src) {
    asm volatile("cp.async.cg.shared.global [%0], [%1], 16;"
                 :: "r"(dst), "l"(src));
}
__device__ __forceinline__ void cpa_commit() {
    asm volatile("cp.async.commit_group;" ::: "memory");
}
template <int N>
__device__ __forceinline__ void cpa_wait() {
    asm volatile("cp.async.wait_group %0;" :: "n"(N) : "memory");
}

__device__ __forceinline__ void mma_tf32(float& c0, float& c1, float& c2, float& c3,
                                         uint32_t a0, uint32_t a1, uint32_t a2, uint32_t a3,
                                         uint32_t b0, uint32_t b1) {
    asm volatile(
        "mma.sync.aligned.m16n8k8.row.col.f32.tf32.tf32.f32 "
        "{%0,%1,%2,%3}, {%4,%5,%6,%7}, {%8,%9}, {%0,%1,%2,%3};"
        : "+f"(c0), "+f"(c1), "+f"(c2), "+f"(c3)
        : "r"(a0), "r"(a1), "r"(a2), "r"(a3), "r"(b0), "r"(b1));
}

// A frag packing: tile=(row>>4)*KBLKS+(k>>3); lane=(r&7)*4+(c&3);
// slot=((r>>3)&1) | (((c>>2)&1)<<1); off = tile*128 + lane*4 + slot
__device__ __forceinline__ size_t a_pk_idx(int row, int k) {
    int r = row & 15, c = k & 7;
    int lane = (r & 7) * 4 + (c & 3);
    int slot = ((r >> 3) & 1) | (((c >> 2) & 1) << 1);
    return ((size_t)(row >> 4) * KBLKS + (k >> 3)) * 128 + lane * 4 + slot;
}
// B frag packing: tile=(n>>3)*KBLKS+(k>>3); lane=(n&7)*4+(k&3); slot=(k>>2)&1
__device__ __forceinline__ size_t b_pk_idx(int n, int k) {
    int lane = (n & 7) * 4 + (k & 3);
    int slot = (k >> 2) & 1;
    return ((size_t)(n >> 3) * KBLKS + (k >> 3)) * 64 + lane * 2 + slot;
}

// ---------------------------------------------------------------------------
// Kernel 1: conv3x3(1->5)+BN+ReLU+maxpool3x3/3 -> plain h + tf32 frag-packed A
// ---------------------------------------------------------------------------
__global__ __launch_bounds__(320) void conv_bn_pool_kernel(
    const float* __restrict__ x, const float* __restrict__ conv_w,
    const float* __restrict__ gamma, const float* __restrict__ beta,
    const float* __restrict__ mean, const float* __restrict__ var)
{
    __shared__ float xs[28 * 28];
    const int b   = blockIdx.x;
    const int tid = threadIdx.x;

    const float* xb = x + (size_t)b * 784;
    for (int i = tid; i < 784; i += 320) xs[i] = xb[i];
    __syncthreads();

    const int c   = tid >> 6;
    const int rem = tid & 63;
    const int py  = rem >> 3;
    const int px  = rem & 7;

    float w[9];
#pragma unroll
    for (int i = 0; i < 9; i++) w[i] = conv_w[c * 9 + i];
    const float sc = gamma[c] * rsqrtf(var[c] + 1e-5f);
    const float mu = mean[c];
    const float bt = beta[c];

    const int oy0 = py * 3, ox0 = px * 3;
    float m = -3.4e38f;
#pragma unroll
    for (int dy = 0; dy < 3; dy++) {
#pragma unroll
        for (int dx = 0; dx < 3; dx++) {
            const int iy = oy0 + dy, ix = ox0 + dx;
            float s = 0.f;
#pragma unroll
            for (int ky = 0; ky < 3; ky++)
#pragma unroll
                for (int kx = 0; kx < 3; kx++)
                    s += xs[(iy + ky) * 28 + (ix + kx)] * w[ky * 3 + kx];
            m = fmaxf(m, (s - mu) * sc + bt);
        }
    }
    float v = fmaxf(m, 0.f);
    g_h[(size_t)b * KDIM + tid] = v;
    g_Apk[a_pk_idx(b, tid)]     = tf32r(v);
}

// ---------------------------------------------------------------------------
// Kernel 1b: fc_w -> tf32 frag-packed B
// ---------------------------------------------------------------------------
__global__ __launch_bounds__(256) void decompB_kernel(const float* __restrict__ w)
{
    const int i = blockIdx.x * 256 + threadIdx.x;   // over EMB*KDIM
    const int n = i / KDIM;
    const int k = i - n * KDIM;
    g_Bpk[b_pk_idx(n, k)] = tf32r(w[i]);
}

// ---------------------------------------------------------------------------
// Kernel 2: z ~= h @ fc_w^T via mma.sync tf32 (1 term), 3-stage cp.async
// CTA 128x256, 8 warps (2m x 4n), warp tile 64x64.
// ---------------------------------------------------------------------------
#define OFFB  16384
#define STAGE 49152            // A 16KB + B 32KB
#define SMEM_TOTAL (3 * STAGE) // 144KB

__global__ void __launch_bounds__(256, 1) gemm_tc_kernel()
{
    extern __shared__ char smem[];
    const uint32_t sb = smem_u32(smem);
    const int tid  = threadIdx.x;
    const int lane = tid & 31;
    const int wid  = tid >> 5;
    const int wm   = wid & 1;
    const int wn   = wid >> 1;
    const int bn   = blockIdx.x;    // 0..7
    const int bm   = blockIdx.y;    // 0..255

    const int rb0 = bm * 8;         // A rowblk base
    const int nb0 = bn * 32;        // B nblk base

    auto issue_stage = [&](int ch, int s) {
        const int kb0 = ch * 4;
        const uint32_t sbase = sb + s * STAGE;
#pragma unroll
        for (int i = 0; i < 4; i++) {               // A: 1024 x 16B
            const int idx  = tid + i * 256;
            const int tile = idx >> 5;              // rowblk_l*4 + kblk_l
            const int l    = idx & 31;
            const float* src = g_Apk
                + ((size_t)(rb0 + (tile >> 2)) * KBLKS + kb0 + (tile & 3)) * 128 + l * 4;
            cpa16(sbase + tile * 512 + l * 16, src);
        }
#pragma unroll
        for (int i = 0; i < 8; i++) {               // B: 2048 x 16B
            const int idx  = tid + i * 256;
            const int tile = idx >> 4;              // nblk_l*4 + kblk_l
            const int l    = idx & 15;
            const float* src = g_Bpk
                + ((size_t)(nb0 + (tile >> 2)) * KBLKS + kb0 + (tile & 3)) * 64 + l * 4;
            cpa16(sbase + OFFB + tile * 256 + l * 16, src);
        }
        cpa_commit();
    };

    float acc[4][8][4];
#pragma unroll
    for (int i = 0; i < 4; i++)
#pragma unroll
        for (int j = 0; j < 8; j++)
#pragma unroll
            for (int q = 0; q < 4; q++) acc[i][j][q] = 0.f;

    issue_stage(0, 0);
    issue_stage(1, 1);
    issue_stage(2, 2);

    for (int ch = 0; ch < CHUNKS; ch++) {
        if (ch <= CHUNKS - 3)      cpa_wait<2>();
        else if (ch == CHUNKS - 2) cpa_wait<1>();
        else                       cpa_wait<0>();
        __syncthreads();

        const int s = ch - (ch / 3) * 3;
        const uint32_t abase = sb + s * STAGE;
        const uint32_t bbase = abase + OFFB;

#pragma unroll
        for (int kt = 0; kt < 4; kt++) {
            uint32_t ah[4][4];
#pragma unroll
            for (int mt = 0; mt < 4; mt++) {
                const uint32_t off = ((wm * 4 + mt) * 4 + kt) * 512 + lane * 16;
                asm volatile("ld.shared.v4.b32 {%0,%1,%2,%3}, [%4];"
                             : "=r"(ah[mt][0]), "=r"(ah[mt][1]), "=r"(ah[mt][2]), "=r"(ah[mt][3])
                             : "r"(abase + off));
            }
#pragma unroll
            for (int nt = 0; nt < 8; nt++) {
                const uint32_t boff = ((wn * 8 + nt) * 4 + kt) * 256 + lane * 8;
                uint32_t b0, b1;
                asm volatile("ld.shared.v2.b32 {%0,%1}, [%2];"
                             : "=r"(b0), "=r"(b1) : "r"(bbase + boff));
#pragma unroll
                for (int mt = 0; mt < 4; mt++) {
                    mma_tf32(acc[mt][nt][0], acc[mt][nt][1], acc[mt][nt][2], acc[mt][nt][3],
                             ah[mt][0], ah[mt][1], ah[mt][2], ah[mt][3], b0, b1);
                }
            }
        }
        __syncthreads();
        if (ch + 3 < CHUNKS) issue_stage(ch + 3, (ch + 3) - ((ch + 3) / 3) * 3);
    }

    // Epilogue: direct coalesced stores
    const int g = lane >> 2;
    const int t = lane & 3;
    const int row0 = bm * 128 + wm * 64;
    const int col0 = bn * 256 + wn * 64;
#pragma unroll
    for (int mt = 0; mt < 4; mt++) {
        const int row = row0 + mt * 16 + g;
#pragma unroll
        for (int nt = 0; nt < 8; nt++) {
            const int col = col0 + nt * 8 + t * 2;
            *(float2*)(g_z + (size_t)row * EMB + col)
                = make_float2(acc[mt][nt][0], acc[mt][nt][1]);
            *(float2*)(g_z + (size_t)(row + 8) * EMB + col)
                = make_float2(acc[mt][nt][2], acc[mt][nt][3]);
        }
    }
}

// ---------------------------------------------------------------------------
// Kernel 3: radix-select threshold on approx z + exact fp32 refinement of the
// boundary window + binarize. Refinement uses a strictly SEQUENTIAL k-ascending
// fp32 FMA chain (one thread per candidate) to match the reference GEMM's
// accumulation topology on near-tie boundary pairs.
// ---------------------------------------------------------------------------
__device__ __forceinline__ unsigned f2key(float f)
{
    unsigned u = __float_as_uint(f);
    return (u & 0x80000000u) ? ~u : (u | 0x80000000u);
}
__device__ __forceinline__ float key2f(unsigned k)
{
    unsigned u = (k & 0x80000000u) ? (k & 0x7FFFFFFFu) : ~k;
    return __uint_as_float(u);
}

__global__ __launch_bounds__(256) void kwta_kernel(
    const float* __restrict__ fc_w, float* __restrict__ out)
{
    __shared__ unsigned hist[256];
    __shared__ unsigned scan[256];
    __shared__ unsigned sh_bin;
    __shared__ unsigned sh_k;
    __shared__ int s_above, s_nc;
    __shared__ int   s_cid[MAXC];
    __shared__ float s_cz [MAXC];
    __shared__ unsigned char s_sel[MAXC];
    __shared__ float s_h[KDIM];

    const int row = blockIdx.x;
    const int tid = threadIdx.x;

    const float4* zr = (const float4*)(g_z + (size_t)row * EMB);
    float4 v0 = zr[tid * 2];
    float4 v1 = zr[tid * 2 + 1];
    float zv[8] = {v0.x, v0.y, v0.z, v0.w, v1.x, v1.y, v1.z, v1.w};

    // stage h row for refinement
    if (tid < 160) {
        const float2 hv = *(const float2*)(g_h + (size_t)row * KDIM + tid * 2);
        s_h[tid * 2]     = hv.x;
        s_h[tid * 2 + 1] = hv.y;
    }

    unsigned key[8];
#pragma unroll
    for (int e = 0; e < 8; e++) key[e] = f2key(zv[e]);

    unsigned prefix = 0;
    unsigned k = K_ACTIVE;

#pragma unroll
    for (int shift = 24; shift >= 0; shift -= 8) {
        hist[tid] = 0;
        __syncthreads();
#pragma unroll
        for (int e = 0; e < 8; e++) {
            bool match = (shift == 24) ? true : ((key[e] >> (shift + 8)) == prefix);
            if (match) atomicAdd(&hist[(key[e] >> shift) & 255u], 1u);
        }
        __syncthreads();

        scan[tid] = hist[tid];
        __syncthreads();
#pragma unroll
        for (int off = 1; off < 256; off <<= 1) {
            unsigned add = (tid + off < 256) ? scan[tid + off] : 0u;
            __syncthreads();
            scan[tid] += add;
            __syncthreads();
        }

        unsigned St    = scan[tid];
        unsigned Snext = (tid < 255) ? scan[tid + 1] : 0u;
        if (St >= k && Snext < k) {
            sh_bin = (unsigned)tid;
            sh_k   = k - Snext;
        }
        __syncthreads();
        prefix = (prefix << 8) | sh_bin;
        k = sh_k;
        __syncthreads();
    }

    // Approx threshold in float domain; refinement window
    const float thrf = key2f(prefix);
    const float wlo  = thrf - DELTA;
    const float whi  = thrf + DELTA;

    if (tid == 0) { s_above = 0; s_nc = 0; }
    __syncthreads();

    int myAbove = 0;
#pragma unroll
    for (int e = 0; e < 8; e++) {
        if (zv[e] > whi) myAbove++;
        else if (zv[e] >= wlo) {
            int idx = atomicAdd(&s_nc, 1);
            if (idx < MAXC) s_cid[idx] = tid * 8 + e;
        }
    }
    if (myAbove) atomicAdd(&s_above, myAbove);
    __syncthreads();

    const int nc   = min(s_nc, MAXC);
    const int need = K_ACTIVE - s_above;

    // Sequential fp32 recompute: one THREAD per candidate, k ascending.
    for (int c = tid; c < nc; c += 256) {
        const int j = s_cid[c];
        const float* wr = fc_w + (size_t)j * KDIM;
        float s = 0.f;
#pragma unroll 16
        for (int kk = 0; kk < KDIM; kk++)
            s = fmaf(s_h[kk], wr[kk], s);
        s_cz[c] = s;
    }
    __syncthreads();

    // Select 'need' largest among candidates by exact value (tie -> include)
    for (int i = tid; i < nc; i += 256) {
        int cg = 0;
        for (int j = 0; j < nc; j++) cg += (s_cz[j] > s_cz[i]);
        s_sel[i] = (cg < need) ? 1 : 0;
    }
    __syncthreads();

    // Bulk write: above window -> 1, everything else (incl. window) -> 0
    float4 o0, o1;
    o0.x = (zv[0] > whi) ? 1.f : 0.f;
    o0.y = (zv[1] > whi) ? 1.f : 0.f;
    o0.z = (zv[2] > whi) ? 1.f : 0.f;
    o0.w = (zv[3] > whi) ? 1.f : 0.f;
    o1.x = (zv[4] > whi) ? 1.f : 0.f;
    o1.y = (zv[5] > whi) ? 1.f : 0.f;
    o1.z = (zv[6] > whi) ? 1.f : 0.f;
    o1.w = (zv[7] > whi) ? 1.f : 0.f;
    float4* od = (float4*)(out + (size_t)row * EMB);
    od[tid * 2]     = o0;
    od[tid * 2 + 1] = o1;
    __syncthreads();

    // Overwrite window elements with exact decision
    for (int c = tid; c < nc; c += 256)
        out[(size_t)row * EMB + s_cid[c]] = s_sel[c] ? 1.f : 0.f;
}

// ---------------------------------------------------------------------------
extern "C" void kernel_launch(void* const* d_in, const int* in_sizes, int n_in,
                              void* d_out, int out_size)
{
    const float* x      = (const float*)d_in[0];
    const float* conv_w = (const float*)d_in[1];
    const float* gamma  = (const float*)d_in[2];
    const float* beta   = (const float*)d_in[3];
    const float* mean   = (const float*)d_in[4];
    const float* var    = (const float*)d_in[5];
    const float* fc_w   = (const float*)d_in[6];
    float* out = (float*)d_out;

    cudaFuncSetAttribute(gemm_tc_kernel,
                         cudaFuncAttributeMaxDynamicSharedMemorySize, SMEM_TOTAL);

    conv_bn_pool_kernel<<<BATCH, 320>>>(x, conv_w, gamma, beta, mean, var);
    decompB_kernel<<<(EMB * KDIM) / 256, 256>>>(fc_w);
    gemm_tc_kernel<<<dim3(EMB / TN, BATCH / TM), 256, SMEM_TOTAL>>>();
    kwta_kernel<<<BATCH, 256>>>(fc_w, out);
}